// round 16
// baseline (speedup 1.0000x reference)
#include <cuda_runtime.h>
#include <cuda_fp16.h>
#include <mma.h>
#include <math.h>

using namespace nvcuda;

#define NN 150000
#define EE 2400000
#define BB 16384
#define N_USERS 100000
#define EMB 64
#define HID 128
#define LN_EPS 1e-5f
#define MAXDEG 64   // Poisson(16) in-degree; P(any node > 64) ~ 1e-13, guarded anyway
#define NBLKS 147   // ceil(NN/1024)

// ---------------- static scratch ----------------
__device__ __half d_xs [(size_t)NN * 64];     // fp16(dinv[n] * x[n])
__device__ __half d_ax [(size_t)NN * 64];     // fp16(A_hat @ x)
__device__ __half d_xs2[(size_t)NN * 64];     // fp16(dinv * (relu((A x)W1+b1) W2))
__device__ int    d_pad[(size_t)NN * MAXDEG]; // padded adjacency: BYTE OFFSETS (src<<7)
__device__ __half d_W1h[64 * 128];
__device__ __half d_W2h[128 * 64];
__device__ __half d_fcW1h[128 * 128];
__device__ __half d_fcW2h[128 * 64];
__device__ int    d_counts[NN];
__device__ float  d_dinv[NN];

// ---- padded adjacency build + fused weight conversion ----
// (d_counts pre-zeroed by a cudaMemsetAsync node)
__global__ void k_fillpad(const int* __restrict__ src, const int* __restrict__ dst,
                          const float* __restrict__ W1, const float* __restrict__ W2,
                          const float* __restrict__ fcW1, const float* __restrict__ fcW2) {
    int q = blockIdx.x * blockDim.x + threadIdx.x;
    // weight conversion piggybacked on the first 40960 threads
    if (q < 8192)        d_W1h[q]          = __float2half(W1[q]);
    else if (q < 16384)  d_W2h[q - 8192]   = __float2half(W2[q - 8192]);
    else if (q < 32768)  d_fcW1h[q - 16384] = __float2half(fcW1[q - 16384]);
    else if (q < 40960)  d_fcW2h[q - 32768] = __float2half(fcW2[q - 32768]);

    if (q < EE / 4) {
        int4 d = ((const int4*)dst)[q];
        int4 s = ((const int4*)src)[q];
        int p0 = atomicAdd(&d_counts[d.x], 1);
        if (p0 < MAXDEG) d_pad[(size_t)d.x * MAXDEG + p0] = s.x << 7;
        int p1 = atomicAdd(&d_counts[d.y], 1);
        if (p1 < MAXDEG) d_pad[(size_t)d.y * MAXDEG + p1] = s.y << 7;
        int p2 = atomicAdd(&d_counts[d.z], 1);
        if (p2 < MAXDEG) d_pad[(size_t)d.z * MAXDEG + p2] = s.z << 7;
        int p3 = atomicAdd(&d_counts[d.w], 1);
        if (p3 < MAXDEG) d_pad[(size_t)d.w * MAXDEG + p3] = s.w << 7;
    }
}

// prep: dinv from final counts + fused prescale d_xs = fp16(dinv * x)
__global__ void k_prep(const float* __restrict__ x) {
    __shared__ float sdinv[1024];
    int b = blockIdx.x, t = threadIdx.x;
    int i = b * 1024 + t;
    float di = 0.f;
    if (i < NN) {
        di = rsqrtf(1.0f + (float)d_counts[i]);
        d_dinv[i] = di;
    }
    sdinv[t] = di;
    __syncthreads();
    int nb = b * 1024;
    for (int e = t; e < 1024 * 32; e += 1024) {
        int node = nb + (e >> 5);
        if (node < NN) {
            float2 vx = ((const float2*)x)[(size_t)node * 32 + (e & 31)];
            float d = sdinv[e >> 5];
            ((__half2*)d_xs)[(size_t)node * 32 + (e & 31)] =
                __floats2half2_rn(vx.x * d, vx.y * d);
        }
    }
}

// ---- warp-collective gather: lane-parallel index preload, shuffle-
// distributed byte offsets, dual HADD2 chains. Returns self+neighbor sum. ----
__device__ __forceinline__ float2 gather_sum(const char* lb, int lane, int node,
                                             int cnt, const int* __restrict__ adj) {
    __half2 acc0 = *(const __half2*)(lb + ((size_t)node << 7));   // self
    __half2 acc1 = __floats2half2_rn(0.f, 0.f);
    int off0 = __ldg(&adj[lane]);            // one LDG covers 32 offsets
    int m = min(cnt, 32);
    int j = 0;
    for (; j + 1 < m; j += 2) {
        int oa = __shfl_sync(0xffffffffu, off0, j);
        int ob = __shfl_sync(0xffffffffu, off0, j + 1);
        acc0 = __hadd2(acc0, *(const __half2*)(lb + oa));
        acc1 = __hadd2(acc1, *(const __half2*)(lb + ob));
    }
    if (j < m) {
        int oa = __shfl_sync(0xffffffffu, off0, j);
        acc0 = __hadd2(acc0, *(const __half2*)(lb + oa));
    }
    if (cnt > 32) {                           // rare (~1e-4 of nodes)
        int off1 = __ldg(&adj[32 + lane]);
        int k = 32;
        for (; k + 1 < cnt; k += 2) {
            int oa = __shfl_sync(0xffffffffu, off1, k - 32);
            int ob = __shfl_sync(0xffffffffu, off1, k - 31);
            acc0 = __hadd2(acc0, *(const __half2*)(lb + oa));
            acc1 = __hadd2(acc1, *(const __half2*)(lb + ob));
        }
        if (k < cnt) {
            int oa = __shfl_sync(0xffffffffu, off1, k - 32);
            acc0 = __hadd2(acc0, *(const __half2*)(lb + oa));
        }
    }
    float2 a0 = __half22float2(acc0);
    float2 a1 = __half22float2(acc1);
    return make_float2(a0.x + a1.x, a0.y + a1.y);
}

// ---- aggregation layer 1: warp per node ----
__global__ void k_agg1() {
    int gw   = (blockIdx.x * blockDim.x + threadIdx.x) >> 5;
    int lane = threadIdx.x & 31;
    if (gw >= NN) return;
    int cnt = min(d_counts[gw], MAXDEG);
    const int* adj = &d_pad[(size_t)gw * MAXDEG];
    const char* lb = (const char*)d_xs + lane * 4;
    float2 s = gather_sum(lb, lane, gw, cnt, adj);
    float di = d_dinv[gw];
    ((__half2*)d_ax)[(size_t)gw * 32 + lane] =
        __floats2half2_rn(di * s.x, di * s.y);
}

// ---- fused GEMM (wmma): xs2 = fp16(dinv * (relu(ax@W1 + b1) @ W2)) --------
__global__ __launch_bounds__(256) void k_gemm_fused(const float* __restrict__ b1) {
    __shared__ __align__(16) char pool[49152];
    __half* As = (__half*)pool;
    __half* Bs = (__half*)(pool + 8192);
    __half* Hs = (__half*)(pool + 24576);
    int t = threadIdx.x;
    int rowbase = blockIdx.x * 64;
    int w  = t >> 5, lane = t & 31;
    int wr = w >> 1;
    int wc = w & 1;
    float* St = (float*)pool + w * 288;

    for (int i = t; i < 64 * 32; i += 256) {
        int row = rowbase + (i >> 5);
        ((__half2*)As)[i] = (row < NN) ? ((const __half2*)d_ax)[(size_t)rowbase * 32 + i]
                                       : __floats2half2_rn(0.f, 0.f);
    }
    for (int i = t; i < 4096; i += 256)
        ((__half2*)Bs)[i] = ((const __half2*)d_W1h)[i];
    __syncthreads();

    wmma::fragment<wmma::accumulator, 16, 16, 16, float> cf[4];
    #pragma unroll
    for (int j = 0; j < 4; j++) wmma::fill_fragment(cf[j], 0.0f);
    #pragma unroll
    for (int k = 0; k < 4; k++) {
        wmma::fragment<wmma::matrix_a, 16, 16, 16, __half, wmma::row_major> af;
        wmma::load_matrix_sync(af, As + (wr * 16) * 64 + k * 16, 64);
        #pragma unroll
        for (int j = 0; j < 4; j++) {
            wmma::fragment<wmma::matrix_b, 16, 16, 16, __half, wmma::row_major> bf;
            wmma::load_matrix_sync(bf, Bs + (k * 16) * 128 + wc * 64 + j * 16, 128);
            wmma::mma_sync(cf[j], af, bf, cf[j]);
        }
    }
    __syncthreads();

    #pragma unroll
    for (int j = 0; j < 4; j++) {
        wmma::store_matrix_sync(St, cf[j], 18, wmma::mem_row_major);
        __syncwarp();
        int colbase = wc * 64 + j * 16;
        for (int i = lane; i < 128; i += 32) {
            int lr = i >> 3, c2 = (i & 7) * 2;
            float v0 = fmaxf(St[lr * 18 + c2]     + b1[colbase + c2], 0.f);
            float v1 = fmaxf(St[lr * 18 + c2 + 1] + b1[colbase + c2 + 1], 0.f);
            ((__half2*)Hs)[(wr * 16 + lr) * 64 + (colbase >> 1) + (i & 7)] =
                __floats2half2_rn(v0, v1);
        }
        __syncwarp();
    }
    __syncthreads();

    for (int i = t; i < 4096; i += 256)
        ((__half2*)Bs)[i] = ((const __half2*)d_W2h)[i];
    __syncthreads();

    wmma::fragment<wmma::accumulator, 16, 16, 16, float> cf2[2];
    #pragma unroll
    for (int j = 0; j < 2; j++) wmma::fill_fragment(cf2[j], 0.0f);
    #pragma unroll
    for (int k = 0; k < 8; k++) {
        wmma::fragment<wmma::matrix_a, 16, 16, 16, __half, wmma::row_major> af;
        wmma::load_matrix_sync(af, Hs + (wr * 16) * 128 + k * 16, 128);
        #pragma unroll
        for (int j = 0; j < 2; j++) {
            wmma::fragment<wmma::matrix_b, 16, 16, 16, __half, wmma::row_major> bf;
            wmma::load_matrix_sync(bf, Bs + (k * 16) * 64 + wc * 32 + j * 16, 64);
            wmma::mma_sync(cf2[j], af, bf, cf2[j]);
        }
    }
    __syncthreads();

    #pragma unroll
    for (int j = 0; j < 2; j++) {
        wmma::store_matrix_sync(St, cf2[j], 18, wmma::mem_row_major);
        __syncwarp();
        int colbase = wc * 32 + j * 16;
        for (int i = lane; i < 128; i += 32) {
            int lr = i >> 3, c2 = (i & 7) * 2;
            int row = rowbase + wr * 16 + lr;
            if (row < NN) {
                float di = d_dinv[row];
                float v0 = di * St[lr * 18 + c2];
                float v1 = di * St[lr * 18 + c2 + 1];
                ((__half2*)d_xs2)[(size_t)row * 32 + (colbase >> 1) + (i & 7)] =
                    __floats2half2_rn(v0, v1);
            }
        }
        __syncwarp();
    }
}

// ------ fused layer-2 agg + MLP head: 8 rows/block, fp16 weights ------------
__global__ __launch_bounds__(256) void k_mlp(
        const int* __restrict__ ui, const int* __restrict__ ii,
        const float* __restrict__ b2,
        const float* __restrict__ fcb1,
        const float* __restrict__ g1,   const float* __restrict__ be1,
        const float* __restrict__ fcb2,
        const float* __restrict__ g2,   const float* __restrict__ be2,
        const float* __restrict__ fcW3, const float* __restrict__ fcb3,
        float* __restrict__ out) {
    __shared__ float cs[8][128];
    __shared__ float zs[8][128];
    __shared__ float rS[8][2], rQ[8][2];
    int t = threadIdx.x, lane = t & 31, w = t >> 5;
    int r0 = blockIdx.x * 8;

    {
        int row = r0 + w;
        const char* lb = (const char*)d_xs2 + lane * 4;
        float2 bv = ((const float2*)b2)[lane];
        int nodeU = ui[row] - 1;
        int nodeI = ii[row] - 1 + N_USERS;
        int cntU = min(d_counts[nodeU], MAXDEG);
        int cntI = min(d_counts[nodeI], MAXDEG);
        float2 su = gather_sum(lb, lane, nodeU, cntU, &d_pad[(size_t)nodeU * MAXDEG]);
        float2 si = gather_sum(lb, lane, nodeI, cntI, &d_pad[(size_t)nodeI * MAXDEG]);
        float diU = d_dinv[nodeU], diI = d_dinv[nodeI];
        cs[w][lane * 2]          = diU * su.x + bv.x;
        cs[w][lane * 2 + 1]      = diU * su.y + bv.y;
        cs[w][64 + lane * 2]     = diI * si.x + bv.x;
        cs[w][64 + lane * 2 + 1] = diI * si.y + bv.y;
    }
    __syncthreads();

    int c2 = t & 63;
    int g  = t >> 6;
    int wg = w & 1;
    const __half2* W1h = (const __half2*)d_fcW1h;
    float2 b1v = ((const float2*)fcb1)[c2];
    float a0x = b1v.x, a0y = b1v.y, a1x = b1v.x, a1y = b1v.y;
    #pragma unroll 8
    for (int k = 0; k < 128; k++) {
        float2 wv = __half22float2(W1h[k * 64 + c2]);
        float v0 = cs[2 * g][k], v1 = cs[2 * g + 1][k];
        a0x = fmaf(v0, wv.x, a0x); a0y = fmaf(v0, wv.y, a0y);
        a1x = fmaf(v1, wv.x, a1x); a1y = fmaf(v1, wv.y, a1y);
    }
    float s0 = a0x + a0y, q0 = a0x * a0x + a0y * a0y;
    float s1 = a1x + a1y, q1 = a1x * a1x + a1y * a1y;
    #pragma unroll
    for (int o = 16; o; o >>= 1) {
        s0 += __shfl_xor_sync(0xffffffffu, s0, o);
        q0 += __shfl_xor_sync(0xffffffffu, q0, o);
        s1 += __shfl_xor_sync(0xffffffffu, s1, o);
        q1 += __shfl_xor_sync(0xffffffffu, q1, o);
    }
    if (lane == 0) {
        rS[2 * g][wg] = s0; rQ[2 * g][wg] = q0;
        rS[2 * g + 1][wg] = s1; rQ[2 * g + 1][wg] = q1;
    }
    __syncthreads();
    {
        float2 g1v = ((const float2*)g1)[c2];
        float2 be1v = ((const float2*)be1)[c2];
        float S0 = rS[2 * g][0] + rS[2 * g][1];
        float Q0 = rQ[2 * g][0] + rQ[2 * g][1];
        float S1 = rS[2 * g + 1][0] + rS[2 * g + 1][1];
        float Q1 = rQ[2 * g + 1][0] + rQ[2 * g + 1][1];
        float m0 = S0 * (1.f / 128.f), v0 = Q0 * (1.f / 128.f) - m0 * m0;
        float m1 = S1 * (1.f / 128.f), v1 = Q1 * (1.f / 128.f) - m1 * m1;
        float r0s = rsqrtf(v0 + LN_EPS), r1s = rsqrtf(v1 + LN_EPS);
        float z0x = fmaxf((a0x - m0) * r0s * g1v.x + be1v.x, 0.f);
        float z0y = fmaxf((a0y - m0) * r0s * g1v.y + be1v.y, 0.f);
        float z1x = fmaxf((a1x - m1) * r1s * g1v.x + be1v.x, 0.f);
        float z1y = fmaxf((a1y - m1) * r1s * g1v.y + be1v.y, 0.f);
        ((float2*)zs[2 * g])[c2]     = make_float2(z0x, z0y);
        ((float2*)zs[2 * g + 1])[c2] = make_float2(z1x, z1y);
    }
    __syncthreads();

    {
        const __half2* W2h = (const __half2*)d_fcW2h;
        float2 b2v = ((const float2*)fcb2)[lane];
        float ax = b2v.x, ay = b2v.y;
        #pragma unroll 8
        for (int k = 0; k < 128; k++) {
            float2 wv = __half22float2(W2h[k * 32 + lane]);
            float v = zs[w][k];
            ax = fmaf(v, wv.x, ax); ay = fmaf(v, wv.y, ay);
        }
        float a = ax + ay, q = ax * ax + ay * ay;
        #pragma unroll
        for (int o = 16; o; o >>= 1) {
            a += __shfl_xor_sync(0xffffffffu, a, o);
            q += __shfl_xor_sync(0xffffffffu, q, o);
        }
        float mean = a * (1.f / 64.f);
        float var  = q * (1.f / 64.f) - mean * mean;
        float rstd = rsqrtf(var + LN_EPS);
        float2 g2v = ((const float2*)g2)[lane];
        float2 be2v = ((const float2*)be2)[lane];
        float2 w3v = ((const float2*)fcW3)[lane];
        float z0 = fmaxf((ax - mean) * rstd * g2v.x + be2v.x, 0.f);
        float z1 = fmaxf((ay - mean) * rstd * g2v.y + be2v.y, 0.f);
        float p = z0 * w3v.x + z1 * w3v.y;
        #pragma unroll
        for (int o = 16; o; o >>= 1)
            p += __shfl_xor_sync(0xffffffffu, p, o);
        if (lane == 0)
            out[r0 + w] = 1.0f / (1.0f + expf(-(p + fcb3[0])));
    }
}

// ---------------- launch ----------------
extern "C" void kernel_launch(void* const* d_in, const int* in_sizes, int n_in,
                              void* d_out, int out_size) {
    const float* x    = (const float*)d_in[0];
    const int*   src  = (const int*)  d_in[1];
    const int*   dst  = (const int*)  d_in[2];
    const int*   uidx = (const int*)  d_in[3];
    const int*   iidx = (const int*)  d_in[4];
    const float* W1   = (const float*)d_in[5];
    const float* b1   = (const float*)d_in[6];
    const float* W2   = (const float*)d_in[7];
    const float* b2   = (const float*)d_in[8];
    const float* fcW1 = (const float*)d_in[9];
    const float* fcb1 = (const float*)d_in[10];
    const float* g1   = (const float*)d_in[11];
    const float* be1  = (const float*)d_in[12];
    const float* fcW2 = (const float*)d_in[13];
    const float* fcb2 = (const float*)d_in[14];
    const float* g2   = (const float*)d_in[15];
    const float* be2  = (const float*)d_in[16];
    const float* fcW3 = (const float*)d_in[17];
    const float* fcb3 = (const float*)d_in[18];
    float* out = (float*)d_out;

    // zero counts via memset node (graph-capturable, not a kernel launch)
    void* cptr = nullptr;
    cudaGetSymbolAddress(&cptr, d_counts);
    cudaMemsetAsync(cptr, 0, NN * sizeof(int));

    // padded-adjacency build (+ fused weight conversion), then prep
    k_fillpad<<<(EE / 4 + 255) / 256, 256>>>(src, dst, W1, W2, fcW1, fcW2);
    k_prep<<<NBLKS, 1024>>>(x);

    // layer 1 aggregate (shuffle-indexed HADD2 gathers), fused TC GEMMs
    k_agg1<<<(NN * 32 + 255) / 256, 256>>>();
    k_gemm_fused<<<(NN + 63) / 64, 256>>>(b1);

    // fused agg2 + MLP head (8 pairs per block)
    k_mlp<<<BB / 8, 256>>>(uidx, iidx, b2, fcb1, g1, be1,
                           fcb2, g2, be2, fcW3, fcb3, out);
}

// round 17
// speedup vs baseline: 1.4328x; 1.4328x over previous
#include <cuda_runtime.h>
#include <cuda_fp16.h>
#include <mma.h>
#include <math.h>

using namespace nvcuda;

#define NN 150000
#define EE 2400000
#define BB 16384
#define N_USERS 100000
#define EMB 64
#define HID 128
#define LN_EPS 1e-5f
#define MAXDEG 64   // Poisson(16) in-degree; P(any node > 64) ~ 1e-13, guarded anyway
#define NBLKS 147   // ceil(NN/1024)

// padded smem leading dims (halves): conflict-free ldmatrix (stride%128B != 0)
#define LDA 72      // As: 64 cols + 8 pad
#define LDB1 136    // Bs as W1 [64 x 128]
#define LDB2 72     // Bs as W2 [128 x 64]
#define LDH 136     // Hs: 128 cols + 8 pad

// ---------------- static scratch ----------------
__device__ __half d_xs [(size_t)NN * 64];     // fp16(dinv[n] * x[n])
__device__ __half d_ax [(size_t)NN * 64];     // fp16(A_hat @ x)
__device__ __half d_xs2[(size_t)NN * 64];     // fp16(dinv * (relu((A x)W1+b1) W2))
__device__ int    d_pad[(size_t)NN * MAXDEG]; // padded adjacency: BYTE OFFSETS (src<<7)
__device__ __half d_W1h[64 * 128];
__device__ __half d_W2h[128 * 64];
__device__ __half d_fcW1h[128 * 128];
__device__ __half d_fcW2h[128 * 64];
__device__ int    d_counts[NN];
__device__ float  d_dinv[NN];

// ---- padded adjacency build + fused weight conversion ----
// (d_counts pre-zeroed by a cudaMemsetAsync node)
__global__ void k_fillpad(const int* __restrict__ src, const int* __restrict__ dst,
                          const float* __restrict__ W1, const float* __restrict__ W2,
                          const float* __restrict__ fcW1, const float* __restrict__ fcW2) {
    int q = blockIdx.x * blockDim.x + threadIdx.x;
    if (q < 8192)        d_W1h[q]           = __float2half(W1[q]);
    else if (q < 16384)  d_W2h[q - 8192]    = __float2half(W2[q - 8192]);
    else if (q < 32768)  d_fcW1h[q - 16384] = __float2half(fcW1[q - 16384]);
    else if (q < 40960)  d_fcW2h[q - 32768] = __float2half(fcW2[q - 32768]);

    if (q < EE / 4) {
        int4 d = ((const int4*)dst)[q];
        int4 s = ((const int4*)src)[q];
        int p0 = atomicAdd(&d_counts[d.x], 1);
        if (p0 < MAXDEG) d_pad[(size_t)d.x * MAXDEG + p0] = s.x << 7;
        int p1 = atomicAdd(&d_counts[d.y], 1);
        if (p1 < MAXDEG) d_pad[(size_t)d.y * MAXDEG + p1] = s.y << 7;
        int p2 = atomicAdd(&d_counts[d.z], 1);
        if (p2 < MAXDEG) d_pad[(size_t)d.z * MAXDEG + p2] = s.z << 7;
        int p3 = atomicAdd(&d_counts[d.w], 1);
        if (p3 < MAXDEG) d_pad[(size_t)d.w * MAXDEG + p3] = s.w << 7;
    }
}

// prep: dinv from final counts + fused prescale d_xs = fp16(dinv * x)
__global__ void k_prep(const float* __restrict__ x) {
    __shared__ float sdinv[1024];
    int b = blockIdx.x, t = threadIdx.x;
    int i = b * 1024 + t;
    float di = 0.f;
    if (i < NN) {
        di = rsqrtf(1.0f + (float)d_counts[i]);
        d_dinv[i] = di;
    }
    sdinv[t] = di;
    __syncthreads();
    int nb = b * 1024;
    for (int e = t; e < 1024 * 32; e += 1024) {
        int node = nb + (e >> 5);
        if (node < NN) {
            float2 vx = ((const float2*)x)[(size_t)node * 32 + (e & 31)];
            float d = sdinv[e >> 5];
            ((__half2*)d_xs)[(size_t)node * 32 + (e & 31)] =
                __floats2half2_rn(vx.x * d, vx.y * d);
        }
    }
}

// ---- aggregation layer 1: warp per node, byte-offset gathers, HADD2 -------
__global__ void k_agg1() {
    int gw   = (blockIdx.x * blockDim.x + threadIdx.x) >> 5;
    int lane = threadIdx.x & 31;
    if (gw >= NN) return;
    int cnt = min(d_counts[gw], MAXDEG);
    const int* adj = &d_pad[(size_t)gw * MAXDEG];
    const char* lb = (const char*)d_xs + lane * 4;
    __half2 acc0 = *(const __half2*)(lb + ((size_t)gw << 7));   // self
    __half2 acc1 = __floats2half2_rn(0.f, 0.f);
    int j = 0;
    #pragma unroll 2
    for (; j + 1 < cnt; j += 2) {
        int2 ss = *(const int2*)&adj[j];
        __half2 v0 = *(const __half2*)(lb + ss.x);
        __half2 v1 = *(const __half2*)(lb + ss.y);
        acc0 = __hadd2(acc0, v0);
        acc1 = __hadd2(acc1, v1);
    }
    if (j < cnt)
        acc0 = __hadd2(acc0, *(const __half2*)(lb + __ldg(&adj[j])));
    float2 a0 = __half22float2(acc0);
    float2 a1 = __half22float2(acc1);
    float di = d_dinv[gw];
    ((__half2*)d_ax)[(size_t)gw * 32 + lane] =
        __floats2half2_rn(di * (a0.x + a1.x), di * (a0.y + a1.y));
}

// ---- fused GEMM (wmma, PADDED tiles): xs2 = fp16(dinv*(relu(ax@W1+b1)@W2)) --
// pool: As [0,9216) 64xLDA | Bs [9216,27648) W1 64xLDB1 / W2 128xLDB2
//       Hs [27648,45056) 64xLDH | St aliases As (dead during epilogues)
__global__ __launch_bounds__(256) void k_gemm_fused(const float* __restrict__ b1) {
    __shared__ __align__(16) char pool[45056];
    __half* As = (__half*)pool;
    __half* Bs = (__half*)(pool + 9216);
    __half* Hs = (__half*)(pool + 27648);
    int t = threadIdx.x;
    int rowbase = blockIdx.x * 64;
    int w  = t >> 5, lane = t & 31;
    int wr = w >> 1;
    int wc = w & 1;
    float* St = (float*)pool + w * 288;   // 16x18 fp32 per warp, aliases As

    // load ax tile (ld LDA) + W1 (ld LDB1)
    for (int i = t; i < 64 * 32; i += 256) {
        int row = rowbase + (i >> 5);
        ((__half2*)As)[(i >> 5) * (LDA / 2) + (i & 31)] =
            (row < NN) ? ((const __half2*)d_ax)[(size_t)rowbase * 32 + i]
                       : __floats2half2_rn(0.f, 0.f);
    }
    for (int i = t; i < 4096; i += 256)    // W1: 64 rows x 64 half2
        ((__half2*)Bs)[(i >> 6) * (LDB1 / 2) + (i & 63)] = ((const __half2*)d_W1h)[i];
    __syncthreads();

    // MMA1: h1 = ax @ W1
    wmma::fragment<wmma::accumulator, 16, 16, 16, float> cf[4];
    #pragma unroll
    for (int j = 0; j < 4; j++) wmma::fill_fragment(cf[j], 0.0f);
    #pragma unroll
    for (int k = 0; k < 4; k++) {
        wmma::fragment<wmma::matrix_a, 16, 16, 16, __half, wmma::row_major> af;
        wmma::load_matrix_sync(af, As + (wr * 16) * LDA + k * 16, LDA);
        #pragma unroll
        for (int j = 0; j < 4; j++) {
            wmma::fragment<wmma::matrix_b, 16, 16, 16, __half, wmma::row_major> bf;
            wmma::load_matrix_sync(bf, Bs + (k * 16) * LDB1 + wc * 64 + j * 16, LDB1);
            wmma::mma_sync(cf[j], af, bf, cf[j]);
        }
    }
    __syncthreads();   // As reads done -> St may alias

    // epilogue 1: bias + relu -> Hs (fp16, ld LDH)
    #pragma unroll
    for (int j = 0; j < 4; j++) {
        wmma::store_matrix_sync(St, cf[j], 18, wmma::mem_row_major);
        __syncwarp();
        int colbase = wc * 64 + j * 16;
        for (int i = lane; i < 128; i += 32) {
            int lr = i >> 3, c2 = (i & 7) * 2;
            float v0 = fmaxf(St[lr * 18 + c2]     + b1[colbase + c2], 0.f);
            float v1 = fmaxf(St[lr * 18 + c2 + 1] + b1[colbase + c2 + 1], 0.f);
            ((__half2*)Hs)[(wr * 16 + lr) * (LDH / 2) + (colbase >> 1) + (i & 7)] =
                __floats2half2_rn(v0, v1);
        }
        __syncwarp();
    }
    __syncthreads();   // St dead; Hs complete

    // load W2 (ld LDB2), overwrites W1
    for (int i = t; i < 4096; i += 256)    // W2: 128 rows x 32 half2
        ((__half2*)Bs)[(i >> 5) * (LDB2 / 2) + (i & 31)] = ((const __half2*)d_W2h)[i];
    __syncthreads();

    // MMA2: xs2 = h1 @ W2
    wmma::fragment<wmma::accumulator, 16, 16, 16, float> cf2[2];
    #pragma unroll
    for (int j = 0; j < 2; j++) wmma::fill_fragment(cf2[j], 0.0f);
    #pragma unroll
    for (int k = 0; k < 8; k++) {
        wmma::fragment<wmma::matrix_a, 16, 16, 16, __half, wmma::row_major> af;
        wmma::load_matrix_sync(af, Hs + (wr * 16) * LDH + k * 16, LDH);
        #pragma unroll
        for (int j = 0; j < 2; j++) {
            wmma::fragment<wmma::matrix_b, 16, 16, 16, __half, wmma::row_major> bf;
            wmma::load_matrix_sync(bf, Bs + (k * 16) * LDB2 + wc * 32 + j * 16, LDB2);
            wmma::mma_sync(cf2[j], af, bf, cf2[j]);
        }
    }
    __syncthreads();   // Hs/Bs reads done -> St reuse safe

    // epilogue 2: dinv scale -> d_xs2 (fp16 global)
    #pragma unroll
    for (int j = 0; j < 2; j++) {
        wmma::store_matrix_sync(St, cf2[j], 18, wmma::mem_row_major);
        __syncwarp();
        int colbase = wc * 32 + j * 16;
        for (int i = lane; i < 128; i += 32) {
            int lr = i >> 3, c2 = (i & 7) * 2;
            int row = rowbase + wr * 16 + lr;
            if (row < NN) {
                float di = d_dinv[row];
                float v0 = di * St[lr * 18 + c2];
                float v1 = di * St[lr * 18 + c2 + 1];
                ((__half2*)d_xs2)[(size_t)row * 32 + (colbase >> 1) + (i & 7)] =
                    __floats2half2_rn(v0, v1);
            }
        }
        __syncwarp();
    }
}

// ------ fused layer-2 agg + MLP head: 8 rows/block, fp16 weights ------------
// Phase 1: user+item neighbor lists interleaved -> 4 independent load chains.
__global__ __launch_bounds__(256) void k_mlp(
        const int* __restrict__ ui, const int* __restrict__ ii,
        const float* __restrict__ b2,
        const float* __restrict__ fcb1,
        const float* __restrict__ g1,   const float* __restrict__ be1,
        const float* __restrict__ fcb2,
        const float* __restrict__ g2,   const float* __restrict__ be2,
        const float* __restrict__ fcW3, const float* __restrict__ fcb3,
        float* __restrict__ out) {
    __shared__ float cs[8][128];
    __shared__ float zs[8][128];
    __shared__ float rS[8][2], rQ[8][2];
    int t = threadIdx.x, lane = t & 31, w = t >> 5;
    int r0 = blockIdx.x * 8;

    {
        int row = r0 + w;
        const char* lb = (const char*)d_xs2 + lane * 4;
        float2 bv = ((const float2*)b2)[lane];
        int nodeU = ui[row] - 1;
        int nodeI = ii[row] - 1 + N_USERS;
        int cntU = min(d_counts[nodeU], MAXDEG);
        int cntI = min(d_counts[nodeI], MAXDEG);
        const int* adjU = &d_pad[(size_t)nodeU * MAXDEG];
        const int* adjI = &d_pad[(size_t)nodeI * MAXDEG];
        __half2 aU0 = *(const __half2*)(lb + ((size_t)nodeU << 7));
        __half2 aI0 = *(const __half2*)(lb + ((size_t)nodeI << 7));
        __half2 aU1 = __floats2half2_rn(0.f, 0.f);
        __half2 aI1 = aU1;
        int m = min(cntU, cntI) & ~1;
        int j = 0;
        for (; j < m; j += 2) {
            int2 su = *(const int2*)&adjU[j];
            int2 si = *(const int2*)&adjI[j];
            __half2 u0 = *(const __half2*)(lb + su.x);
            __half2 u1 = *(const __half2*)(lb + su.y);
            __half2 i0 = *(const __half2*)(lb + si.x);
            __half2 i1 = *(const __half2*)(lb + si.y);
            aU0 = __hadd2(aU0, u0);
            aU1 = __hadd2(aU1, u1);
            aI0 = __hadd2(aI0, i0);
            aI1 = __hadd2(aI1, i1);
        }
        int ju = j;
        for (; ju + 1 < cntU; ju += 2) {
            int2 su = *(const int2*)&adjU[ju];
            aU0 = __hadd2(aU0, *(const __half2*)(lb + su.x));
            aU1 = __hadd2(aU1, *(const __half2*)(lb + su.y));
        }
        if (ju < cntU)
            aU0 = __hadd2(aU0, *(const __half2*)(lb + __ldg(&adjU[ju])));
        int ji = j;
        for (; ji + 1 < cntI; ji += 2) {
            int2 si = *(const int2*)&adjI[ji];
            aI0 = __hadd2(aI0, *(const __half2*)(lb + si.x));
            aI1 = __hadd2(aI1, *(const __half2*)(lb + si.y));
        }
        if (ji < cntI)
            aI0 = __hadd2(aI0, *(const __half2*)(lb + __ldg(&adjI[ji])));

        float diU = d_dinv[nodeU], diI = d_dinv[nodeI];
        float2 u0 = __half22float2(aU0), u1 = __half22float2(aU1);
        float2 i0 = __half22float2(aI0), i1 = __half22float2(aI1);
        cs[w][lane * 2]          = diU * (u0.x + u1.x) + bv.x;
        cs[w][lane * 2 + 1]      = diU * (u0.y + u1.y) + bv.y;
        cs[w][64 + lane * 2]     = diI * (i0.x + i1.x) + bv.x;
        cs[w][64 + lane * 2 + 1] = diI * (i0.y + i1.y) + bv.y;
    }
    __syncthreads();

    int c2 = t & 63;
    int g  = t >> 6;
    int wg = w & 1;
    const __half2* W1h = (const __half2*)d_fcW1h;
    float2 b1v = ((const float2*)fcb1)[c2];
    float a0x = b1v.x, a0y = b1v.y, a1x = b1v.x, a1y = b1v.y;
    #pragma unroll 8
    for (int k = 0; k < 128; k++) {
        float2 wv = __half22float2(W1h[k * 64 + c2]);
        float v0 = cs[2 * g][k], v1 = cs[2 * g + 1][k];
        a0x = fmaf(v0, wv.x, a0x); a0y = fmaf(v0, wv.y, a0y);
        a1x = fmaf(v1, wv.x, a1x); a1y = fmaf(v1, wv.y, a1y);
    }
    float s0 = a0x + a0y, q0 = a0x * a0x + a0y * a0y;
    float s1 = a1x + a1y, q1 = a1x * a1x + a1y * a1y;
    #pragma unroll
    for (int o = 16; o; o >>= 1) {
        s0 += __shfl_xor_sync(0xffffffffu, s0, o);
        q0 += __shfl_xor_sync(0xffffffffu, q0, o);
        s1 += __shfl_xor_sync(0xffffffffu, s1, o);
        q1 += __shfl_xor_sync(0xffffffffu, q1, o);
    }
    if (lane == 0) {
        rS[2 * g][wg] = s0; rQ[2 * g][wg] = q0;
        rS[2 * g + 1][wg] = s1; rQ[2 * g + 1][wg] = q1;
    }
    __syncthreads();
    {
        float2 g1v = ((const float2*)g1)[c2];
        float2 be1v = ((const float2*)be1)[c2];
        float S0 = rS[2 * g][0] + rS[2 * g][1];
        float Q0 = rQ[2 * g][0] + rQ[2 * g][1];
        float S1 = rS[2 * g + 1][0] + rS[2 * g + 1][1];
        float Q1 = rQ[2 * g + 1][0] + rQ[2 * g + 1][1];
        float m0 = S0 * (1.f / 128.f), v0 = Q0 * (1.f / 128.f) - m0 * m0;
        float m1 = S1 * (1.f / 128.f), v1 = Q1 * (1.f / 128.f) - m1 * m1;
        float r0s = rsqrtf(v0 + LN_EPS), r1s = rsqrtf(v1 + LN_EPS);
        float z0x = fmaxf((a0x - m0) * r0s * g1v.x + be1v.x, 0.f);
        float z0y = fmaxf((a0y - m0) * r0s * g1v.y + be1v.y, 0.f);
        float z1x = fmaxf((a1x - m1) * r1s * g1v.x + be1v.x, 0.f);
        float z1y = fmaxf((a1y - m1) * r1s * g1v.y + be1v.y, 0.f);
        ((float2*)zs[2 * g])[c2]     = make_float2(z0x, z0y);
        ((float2*)zs[2 * g + 1])[c2] = make_float2(z1x, z1y);
    }
    __syncthreads();

    {
        const __half2* W2h = (const __half2*)d_fcW2h;
        float2 b2v = ((const float2*)fcb2)[lane];
        float ax = b2v.x, ay = b2v.y;
        #pragma unroll 8
        for (int k = 0; k < 128; k++) {
            float2 wv = __half22float2(W2h[k * 32 + lane]);
            float v = zs[w][k];
            ax = fmaf(v, wv.x, ax); ay = fmaf(v, wv.y, ay);
        }
        float a = ax + ay, q = ax * ax + ay * ay;
        #pragma unroll
        for (int o = 16; o; o >>= 1) {
            a += __shfl_xor_sync(0xffffffffu, a, o);
            q += __shfl_xor_sync(0xffffffffu, q, o);
        }
        float mean = a * (1.f / 64.f);
        float var  = q * (1.f / 64.f) - mean * mean;
        float rstd = rsqrtf(var + LN_EPS);
        float2 g2v = ((const float2*)g2)[lane];
        float2 be2v = ((const float2*)be2)[lane];
        float2 w3v = ((const float2*)fcW3)[lane];
        float z0 = fmaxf((ax - mean) * rstd * g2v.x + be2v.x, 0.f);
        float z1 = fmaxf((ay - mean) * rstd * g2v.y + be2v.y, 0.f);
        float p = z0 * w3v.x + z1 * w3v.y;
        #pragma unroll
        for (int o = 16; o; o >>= 1)
            p += __shfl_xor_sync(0xffffffffu, p, o);
        if (lane == 0)
            out[r0 + w] = 1.0f / (1.0f + expf(-(p + fcb3[0])));
    }
}

// ---------------- launch ----------------
extern "C" void kernel_launch(void* const* d_in, const int* in_sizes, int n_in,
                              void* d_out, int out_size) {
    const float* x    = (const float*)d_in[0];
    const int*   src  = (const int*)  d_in[1];
    const int*   dst  = (const int*)  d_in[2];
    const int*   uidx = (const int*)  d_in[3];
    const int*   iidx = (const int*)  d_in[4];
    const float* W1   = (const float*)d_in[5];
    const float* b1   = (const float*)d_in[6];
    const float* W2   = (const float*)d_in[7];
    const float* b2   = (const float*)d_in[8];
    const float* fcW1 = (const float*)d_in[9];
    const float* fcb1 = (const float*)d_in[10];
    const float* g1   = (const float*)d_in[11];
    const float* be1  = (const float*)d_in[12];
    const float* fcW2 = (const float*)d_in[13];
    const float* fcb2 = (const float*)d_in[14];
    const float* g2   = (const float*)d_in[15];
    const float* be2  = (const float*)d_in[16];
    const float* fcW3 = (const float*)d_in[17];
    const float* fcb3 = (const float*)d_in[18];
    float* out = (float*)d_out;

    // zero counts via memset node (graph-capturable, not a kernel launch)
    void* cptr = nullptr;
    cudaGetSymbolAddress(&cptr, d_counts);
    cudaMemsetAsync(cptr, 0, NN * sizeof(int));

    // padded-adjacency build (+ fused weight conversion), then prep
    k_fillpad<<<(EE / 4 + 255) / 256, 256>>>(src, dst, W1, W2, fcW1, fcW2);
    k_prep<<<NBLKS, 1024>>>(x);

    // layer 1 aggregate, then PADDED fused tensor-core GEMMs
    k_agg1<<<(NN * 32 + 255) / 256, 256>>>();
    k_gemm_fused<<<(NN + 63) / 64, 256>>>(b1);

    // fused agg2 + MLP head
    k_mlp<<<BB / 8, 256>>>(uidx, iidx, b2, fcb1, g1, be1,
                           fcb2, g2, be2, fcW3, fcb3, out);
}